// round 13
// baseline (speedup 1.0000x reference)
#include <cuda_runtime.h>
#include <cstdint>

// Problem constants (fixed by the reference)
#define Bn       8
#define Nn       32768
#define CINn     128
#define Mn       (Nn / 4)          // 8192 sampled points
#define CLUSTER  8                 // CTAs per batch (one cluster)
#define PTS_CTA  (Nn / CLUSTER)    // 4096 points per CTA
#define THREADS  512
#define PTS_THR  (PTS_CTA / THREADS) // 8 points per thread
#define PAIRS    (PTS_THR / 2)       // 4 f32x2 pairs per thread
#define NWARPS   (THREADS / 32)      // 16
#define SLOTS    (CLUSTER * NWARPS)  // 128 candidate slots per CTA

// Scratch: selected indices per batch (allowed: __device__ global, no alloc)
__device__ int g_idx[Bn * Mn];

__device__ __forceinline__ uint32_t smem_u32(const void* p) {
    return (uint32_t)__cvta_generic_to_shared(p);
}
__device__ __forceinline__ uint32_t mapa_u32(uint32_t laddr, uint32_t cta) {
    uint32_t r;
    asm("mapa.shared::cluster.u32 %0, %1, %2;" : "=r"(r) : "r"(laddr), "r"(cta));
    return r;
}

// ---- f32x2 packed fp32 helpers (each half = independent rn op, bit-exact) ----
__device__ __forceinline__ void f2_add(unsigned long long& d,
                                       unsigned long long a, unsigned long long b) {
    asm("add.rn.f32x2 %0, %1, %2;" : "=l"(d) : "l"(a), "l"(b));
}
__device__ __forceinline__ void f2_mul(unsigned long long& d,
                                       unsigned long long a, unsigned long long b) {
    asm("mul.rn.f32x2 %0, %1, %2;" : "=l"(d) : "l"(a), "l"(b));
}
__device__ __forceinline__ void f2_fma(unsigned long long& d, unsigned long long a,
                                       unsigned long long b, unsigned long long c) {
    asm("fma.rn.f32x2 %0, %1, %2, %3;" : "=l"(d) : "l"(a), "l"(b), "l"(c));
}
__device__ __forceinline__ unsigned long long f2_pack(float lo, float hi) {
    unsigned long long r;
    asm("mov.b64 %0, {%1, %2};" : "=l"(r) : "f"(lo), "f"(hi));
    return r;
}
__device__ __forceinline__ void f2_unpack(unsigned long long v, float& lo, float& hi) {
    asm("mov.b64 {%0, %1}, %2;" : "=f"(lo), "=f"(hi) : "l"(v));
}
__device__ __forceinline__ unsigned long long u64max(unsigned long long a,
                                                     unsigned long long b) {
    return a > b ? a : b;
}

// ---------------------------------------------------------------------------
// FPS: one 8-CTA cluster per batch, points/distances register-resident.
// Single-level cross-SM argmax: each warp pushes its candidate straight to all
// 8 CTAs (lanes 0-7, precomputed mapa addrs) + mbarrier arrive (count=128).
// Every warp redundantly reduces the 128 slots after the wait — no block
// barriers anywhere in the iteration. Numerics frozen: tie->lowest index,
// d = fma(dz,dz, fma(dx,dx, dy*dy)), dx = px + (-cx).
// ---------------------------------------------------------------------------
__global__ void __cluster_dims__(CLUSTER, 1, 1) __launch_bounds__(THREADS, 1)
fps_kernel(const float* __restrict__ xyz)
{
    __shared__ unsigned long long s_pk[2][SLOTS];   // (dist_bits<<32) | ~idx
    __shared__ unsigned long long s_xy[2][SLOTS];   // packed (x,y)
    __shared__ unsigned           s_z [2][SLOTS];   // z bits
    __shared__ unsigned long long s_mb[2];          // parity mbarriers

    const int tid  = threadIdx.x;
    const int lane = tid & 31;
    const int warp = tid >> 5;
    const int b    = blockIdx.x / CLUSTER;
    const int rank = blockIdx.x % CLUSTER;

    const float* __restrict__ xb = xyz + (size_t)b * 3 * Nn;
    const float* __restrict__ yb = xb + Nn;
    const float* __restrict__ zb = xb + 2 * Nn;
    const int base = rank * PTS_CTA;

    if (tid == 0) {
        asm volatile("mbarrier.init.shared.b64 [%0], %1;"
                     :: "r"(smem_u32(&s_mb[0])), "r"(SLOTS) : "memory");
        asm volatile("mbarrier.init.shared.b64 [%0], %1;"
                     :: "r"(smem_u32(&s_mb[1])), "r"(SLOTS) : "memory");
    }
    asm volatile("barrier.cluster.arrive.aligned;" ::: "memory");

    // Register-resident point slice (f32x2 pairs) + running min-distance
    unsigned long long pxu[PAIRS], pyu[PAIRS], pzu[PAIRS];
    float dist[PTS_THR];
#pragma unroll
    for (int k = 0; k < PAIRS; k++) {
        int g0 = base + (2 * k) * THREADS + tid;
        int g1 = g0 + THREADS;
        pxu[k] = f2_pack(xb[g0], xb[g1]);
        pyu[k] = f2_pack(yb[g0], yb[g1]);
        pzu[k] = f2_pack(zb[g0], zb[g1]);
        dist[2 * k] = 1e10f;
        dist[2 * k + 1] = 1e10f;
    }

    // Precompute remote push addresses (lane l -> CTA l); slot = rank*16+warp
    const int myslot = rank * NWARPS + warp;
    const uint32_t tgt = (uint32_t)(lane & (CLUSTER - 1));
    uint32_t rpk[2], rxy[2], rz[2], rmb[2];
#pragma unroll
    for (int p = 0; p < 2; p++) {
        rpk[p] = mapa_u32(smem_u32(&s_pk[p][myslot]), tgt);
        rxy[p] = mapa_u32(smem_u32(&s_xy[p][myslot]), tgt);
        rz [p] = mapa_u32(smem_u32(&s_z [p][myslot]), tgt);
        rmb[p] = mapa_u32(smem_u32(&s_mb[p]), tgt);
    }
    const uint32_t l_mb[2] = { smem_u32(&s_mb[0]), smem_u32(&s_mb[1]) };

    // Initial farthest = point 0 (reference seeds index 0)
    float c0x = xb[0], c0y = yb[0], c0z = zb[0];
    unsigned long long ncx2 = f2_pack(-c0x, -c0x);
    unsigned long long ncy2 = f2_pack(-c0y, -c0y);
    unsigned long long ncz2 = f2_pack(-c0z, -c0z);
    int far = 0;

    asm volatile("barrier.cluster.wait.aligned;" ::: "memory");

    for (int i = 0; i < Mn; i++) {
        if (rank == 0 && tid == 0) g_idx[b * Mn + i] = far;
        const int parity = i & 1;
        const unsigned phase = (unsigned)((i >> 1) & 1);

        // ---- update distances (f32x2, frozen rounding) + thread argmax ----
        float bd = -1.0f;
        unsigned bi = 0;
#pragma unroll
        for (int k = 0; k < PAIRS; k++) {
            unsigned long long dx2, dy2, dz2, t;
            f2_add(dx2, pxu[k], ncx2);          // px - cx  (exact: a + (-b))
            f2_add(dy2, pyu[k], ncy2);
            f2_add(dz2, pzu[k], ncz2);
            f2_mul(t, dy2, dy2);
            f2_fma(t, dx2, dx2, t);             // fma(dx,dx, dy*dy)
            f2_fma(t, dz2, dz2, t);             // fma(dz,dz, ...)
            float d0, d1;
            f2_unpack(t, d0, d1);
            float nd0 = fminf(dist[2 * k], d0);     dist[2 * k] = nd0;
            float nd1 = fminf(dist[2 * k + 1], d1); dist[2 * k + 1] = nd1;
            unsigned g0 = (unsigned)(base + (2 * k) * THREADS + tid);
            if (nd0 > bd) { bd = nd0; bi = g0; }            // strict >: lowest idx
            if (nd1 > bd) { bd = nd1; bi = g0 + THREADS; }
        }

        // ---- warp argmax (redux): max dist bits, min idx among max ----
        unsigned bits = __float_as_uint(bd);                // bd >= 0 always
        unsigned mx = __reduce_max_sync(0xffffffffu, bits);
        unsigned cand = (bits == mx) ? bi : 0xffffffffu;
        unsigned mn = __reduce_min_sync(0xffffffffu, cand);

        // ---- owner lane extracts winner xyz, broadcast to lanes 0-7 ----
        bool owner = (bits == mx) && (bi == mn);
        float wx = 0.f, wy = 0.f, wz = 0.f;
        if (owner) {
#pragma unroll
            for (int k = 0; k < PAIRS; k++) {
                float ax, ah, ay, yh, az, zh;
                f2_unpack(pxu[k], ax, ah);
                f2_unpack(pyu[k], ay, yh);
                f2_unpack(pzu[k], az, zh);
                unsigned g0 = (unsigned)(base + (2 * k) * THREADS + tid);
                if (g0 == mn)           { wx = ax; wy = ay; wz = az; }
                if (g0 + THREADS == mn) { wx = ah; wy = yh; wz = zh; }
            }
        }
        unsigned bal = __ballot_sync(0xffffffffu, owner);
        int wl = __ffs(bal) - 1;
        wx = __shfl_sync(0xffffffffu, wx, wl);
        wy = __shfl_sync(0xffffffffu, wy, wl);
        wz = __shfl_sync(0xffffffffu, wz, wl);

        // ---- lanes 0-7: push this warp's candidate to CTA `lane` ----
        if (lane < CLUSTER) {
            unsigned long long pk =
                ((unsigned long long)mx << 32) | (unsigned)(~mn);
            unsigned long long xyp = f2_pack(wx, wy);
            asm volatile("st.shared::cluster.b64 [%0], %1;"
                         :: "r"(rpk[parity]), "l"(pk) : "memory");
            asm volatile("st.shared::cluster.b64 [%0], %1;"
                         :: "r"(rxy[parity]), "l"(xyp) : "memory");
            asm volatile("st.shared::cluster.b32 [%0], %1;"
                         :: "r"(rz[parity]), "r"(__float_as_uint(wz)) : "memory");
            asm volatile(
                "mbarrier.arrive.release.cluster.shared::cluster.b64 _, [%0];"
                :: "r"(rmb[parity]) : "memory");
        }

        // ---- wait for all 128 candidates (acquire) ----
        asm volatile(
            "{\n\t.reg .pred P;\n"
            "WAITLP_%=:\n\t"
            "mbarrier.try_wait.parity.acquire.cluster.shared::cta.b64 P, [%0], %1, 0x989680;\n\t"
            "@!P bra WAITLP_%=;\n\t}"
            :: "r"(l_mb[parity]), "r"(phase) : "memory");

        // ---- every warp reduces the 128 slots (no block sync needed) ----
        unsigned long long pk0 = s_pk[parity][lane];
        unsigned long long pk1 = s_pk[parity][lane + 32];
        unsigned long long pk2 = s_pk[parity][lane + 64];
        unsigned long long pk3 = s_pk[parity][lane + 96];
        unsigned long long bp = u64max(u64max(pk0, pk1), u64max(pk2, pk3));

        unsigned hib = (unsigned)(bp >> 32);
        unsigned mx2 = __reduce_max_sync(0xffffffffu, hib);
        unsigned gi  = ~(unsigned)bp;
        unsigned c2  = (hib == mx2) ? gi : 0xffffffffu;
        unsigned mn2 = __reduce_min_sync(0xffffffffu, c2);
        unsigned long long wpk =
            ((unsigned long long)mx2 << 32) | (unsigned)(~mn2);

        int si = -1;
        if (pk0 == wpk) si = lane;
        if (pk1 == wpk) si = lane + 32;
        if (pk2 == wpk) si = lane + 64;
        if (pk3 == wpk) si = lane + 96;
        unsigned bal2 = __ballot_sync(0xffffffffu, si >= 0);
        int sl = __ffs(bal2) - 1;
        int sw = __shfl_sync(0xffffffffu, si, sl);

        far = (int)mn2;
        float ncx, ncy;
        f2_unpack(s_xy[parity][sw], ncx, ncy);
        float ncz = __uint_as_float(s_z[parity][sw]);
        ncx2 = f2_pack(-ncx, -ncx);
        ncy2 = f2_pack(-ncy, -ncy);
        ncz2 = f2_pack(-ncz, -ncz);
    }

    // Drain: no CTA exits while peers may still address its SMEM
    asm volatile("barrier.cluster.arrive.aligned;" ::: "memory");
    asm volatile("barrier.cluster.wait.aligned;" ::: "memory");
}

// ---------------------------------------------------------------------------
// Gather epilogue: out = concat( sampled_xyz [B,3,M], sampled_feature [B,Cin,M] )
// ---------------------------------------------------------------------------
__global__ void gather_kernel(const float* __restrict__ xyz,
                              const float* __restrict__ feat,
                              float* __restrict__ out)
{
    const int P1  = Bn * 3 * Mn;
    const int TOT = P1 + Bn * CINn * Mn;
    int t = blockIdx.x * blockDim.x + threadIdx.x;
    if (t >= TOT) return;
    if (t < P1) {
        int b = t / (3 * Mn);
        int rem = t - b * 3 * Mn;
        int c = rem / Mn;
        int m = rem - c * Mn;
        int idx = g_idx[b * Mn + m];
        out[t] = xyz[(size_t)b * 3 * Nn + (size_t)c * Nn + idx];
    } else {
        int u = t - P1;
        int b = u / (CINn * Mn);
        int rem = u - b * CINn * Mn;
        int c = rem / Mn;
        int m = rem - c * Mn;
        int idx = g_idx[b * Mn + m];
        out[t] = feat[(size_t)b * CINn * Nn + (size_t)c * Nn + idx];
    }
}

extern "C" void kernel_launch(void* const* d_in, const int* in_sizes, int n_in,
                              void* d_out, int out_size)
{
    const float* xyz  = (const float*)d_in[0];  // [B,3,N]
    const float* feat = (const float*)d_in[1];  // [B,Cin,N]
    float* out = (float*)d_out;

    fps_kernel<<<Bn * CLUSTER, THREADS>>>(xyz);

    const int TOT = Bn * 3 * Mn + Bn * CINn * Mn;
    gather_kernel<<<(TOT + 255) / 256, 256>>>(xyz, feat, out);
}

// round 16
// speedup vs baseline: 1.0197x; 1.0197x over previous
#include <cuda_runtime.h>
#include <cstdint>

// Problem constants (fixed by the reference)
#define Bn       8
#define Nn       32768
#define CINn     128
#define Mn       (Nn / 4)          // 8192 sampled points
#define CLUSTER  8                 // CTAs per batch (one cluster)
#define PTS_CTA  (Nn / CLUSTER)    // 4096 points per CTA
#define THREADS  512
#define PTS_THR  (PTS_CTA / THREADS) // 8 points per thread
#define PAIRS    (PTS_THR / 2)       // 4 f32x2 pairs per thread
#define NWARPS   (THREADS / 32)      // 16
#define SLOTS    (CLUSTER * NWARPS)  // 128 candidate slots per CTA

// Scratch: selected indices per batch (allowed: __device__ global, no alloc)
__device__ int g_idx[Bn * Mn];

__device__ __forceinline__ uint32_t smem_u32(const void* p) {
    return (uint32_t)__cvta_generic_to_shared(p);
}
__device__ __forceinline__ uint32_t mapa_u32(uint32_t laddr, uint32_t cta) {
    uint32_t r;
    asm("mapa.shared::cluster.u32 %0, %1, %2;" : "=r"(r) : "r"(laddr), "r"(cta));
    return r;
}

// ---- f32x2 packed fp32 helpers (each half = independent rn op, bit-exact) ----
__device__ __forceinline__ void f2_add(unsigned long long& d,
                                       unsigned long long a, unsigned long long b) {
    asm("add.rn.f32x2 %0, %1, %2;" : "=l"(d) : "l"(a), "l"(b));
}
__device__ __forceinline__ void f2_mul(unsigned long long& d,
                                       unsigned long long a, unsigned long long b) {
    asm("mul.rn.f32x2 %0, %1, %2;" : "=l"(d) : "l"(a), "l"(b));
}
__device__ __forceinline__ void f2_fma(unsigned long long& d, unsigned long long a,
                                       unsigned long long b, unsigned long long c) {
    asm("fma.rn.f32x2 %0, %1, %2, %3;" : "=l"(d) : "l"(a), "l"(b), "l"(c));
}
__device__ __forceinline__ unsigned long long f2_pack(float lo, float hi) {
    unsigned long long r;
    asm("mov.b64 %0, {%1, %2};" : "=l"(r) : "f"(lo), "f"(hi));
    return r;
}
__device__ __forceinline__ void f2_unpack(unsigned long long v, float& lo, float& hi) {
    asm("mov.b64 {%0, %1}, %2;" : "=f"(lo), "=f"(hi) : "l"(v));
}
__device__ __forceinline__ unsigned long long u64max(unsigned long long a,
                                                     unsigned long long b) {
    return a > b ? a : b;
}

// ---------------------------------------------------------------------------
// FPS: one 8-CTA cluster per batch, points/distances register-resident.
// Single-level cross-SM argmax: each warp pushes its candidate straight to all
// 8 CTAs (lanes 0-7, precomputed mapa addrs) + mbarrier arrive (count=128).
// Every warp redundantly reduces the 128 slots after the wait — no block
// barriers anywhere in the iteration. Numerics frozen: tie->lowest index,
// d = fma(dz,dz, fma(dx,dx, dy*dy)), dx = px + (-cx).
// ---------------------------------------------------------------------------
__global__ void __cluster_dims__(CLUSTER, 1, 1) __launch_bounds__(THREADS, 1)
fps_kernel(const float* __restrict__ xyz)
{
    __shared__ unsigned long long s_pk[2][SLOTS];   // (dist_bits<<32) | ~idx
    __shared__ unsigned long long s_xy[2][SLOTS];   // packed (x,y)
    __shared__ unsigned           s_z [2][SLOTS];   // z bits
    __shared__ unsigned long long s_mb[2];          // parity mbarriers

    const int tid  = threadIdx.x;
    const int lane = tid & 31;
    const int warp = tid >> 5;
    const int b    = blockIdx.x / CLUSTER;
    const int rank = blockIdx.x % CLUSTER;

    const float* __restrict__ xb = xyz + (size_t)b * 3 * Nn;
    const float* __restrict__ yb = xb + Nn;
    const float* __restrict__ zb = xb + 2 * Nn;
    const int base = rank * PTS_CTA;

    if (tid == 0) {
        asm volatile("mbarrier.init.shared.b64 [%0], %1;"
                     :: "r"(smem_u32(&s_mb[0])), "r"(SLOTS) : "memory");
        asm volatile("mbarrier.init.shared.b64 [%0], %1;"
                     :: "r"(smem_u32(&s_mb[1])), "r"(SLOTS) : "memory");
    }
    asm volatile("barrier.cluster.arrive.aligned;" ::: "memory");

    // Register-resident point slice (f32x2 pairs) + running min-distance
    unsigned long long pxu[PAIRS], pyu[PAIRS], pzu[PAIRS];
    float dist[PTS_THR];
#pragma unroll
    for (int k = 0; k < PAIRS; k++) {
        int g0 = base + (2 * k) * THREADS + tid;
        int g1 = g0 + THREADS;
        pxu[k] = f2_pack(xb[g0], xb[g1]);
        pyu[k] = f2_pack(yb[g0], yb[g1]);
        pzu[k] = f2_pack(zb[g0], zb[g1]);
        dist[2 * k] = 1e10f;
        dist[2 * k + 1] = 1e10f;
    }

    // Precompute remote push addresses (lane l -> CTA l); slot = rank*16+warp
    const int myslot = rank * NWARPS + warp;
    const uint32_t tgt = (uint32_t)(lane & (CLUSTER - 1));
    uint32_t rpk[2], rxy[2], rz[2], rmb[2];
#pragma unroll
    for (int p = 0; p < 2; p++) {
        rpk[p] = mapa_u32(smem_u32(&s_pk[p][myslot]), tgt);
        rxy[p] = mapa_u32(smem_u32(&s_xy[p][myslot]), tgt);
        rz [p] = mapa_u32(smem_u32(&s_z [p][myslot]), tgt);
        rmb[p] = mapa_u32(smem_u32(&s_mb[p]), tgt);
    }
    const uint32_t l_mb[2] = { smem_u32(&s_mb[0]), smem_u32(&s_mb[1]) };

    // Initial farthest = point 0 (reference seeds index 0)
    float c0x = xb[0], c0y = yb[0], c0z = zb[0];
    unsigned long long ncx2 = f2_pack(-c0x, -c0x);
    unsigned long long ncy2 = f2_pack(-c0y, -c0y);
    unsigned long long ncz2 = f2_pack(-c0z, -c0z);
    int far = 0;

    asm volatile("barrier.cluster.wait.aligned;" ::: "memory");

    for (int i = 0; i < Mn; i++) {
        if (rank == 0 && tid == 0) g_idx[b * Mn + i] = far;
        const int parity = i & 1;
        const unsigned phase = (unsigned)((i >> 1) & 1);

        // ---- update distances (f32x2, frozen rounding) + thread argmax ----
        float bd = -1.0f;
        unsigned bi = 0;
#pragma unroll
        for (int k = 0; k < PAIRS; k++) {
            unsigned long long dx2, dy2, dz2, t;
            f2_add(dx2, pxu[k], ncx2);          // px - cx  (exact: a + (-b))
            f2_add(dy2, pyu[k], ncy2);
            f2_add(dz2, pzu[k], ncz2);
            f2_mul(t, dy2, dy2);
            f2_fma(t, dx2, dx2, t);             // fma(dx,dx, dy*dy)
            f2_fma(t, dz2, dz2, t);             // fma(dz,dz, ...)
            float d0, d1;
            f2_unpack(t, d0, d1);
            float nd0 = fminf(dist[2 * k], d0);     dist[2 * k] = nd0;
            float nd1 = fminf(dist[2 * k + 1], d1); dist[2 * k + 1] = nd1;
            unsigned g0 = (unsigned)(base + (2 * k) * THREADS + tid);
            if (nd0 > bd) { bd = nd0; bi = g0; }            // strict >: lowest idx
            if (nd1 > bd) { bd = nd1; bi = g0 + THREADS; }
        }

        // ---- warp argmax (redux): max dist bits, min idx among max ----
        unsigned bits = __float_as_uint(bd);                // bd >= 0 always
        unsigned mx = __reduce_max_sync(0xffffffffu, bits);
        unsigned cand = (bits == mx) ? bi : 0xffffffffu;
        unsigned mn = __reduce_min_sync(0xffffffffu, cand);

        // ---- owner lane extracts winner xyz, broadcast to lanes 0-7 ----
        bool owner = (bits == mx) && (bi == mn);
        float wx = 0.f, wy = 0.f, wz = 0.f;
        if (owner) {
#pragma unroll
            for (int k = 0; k < PAIRS; k++) {
                float ax, ah, ay, yh, az, zh;
                f2_unpack(pxu[k], ax, ah);
                f2_unpack(pyu[k], ay, yh);
                f2_unpack(pzu[k], az, zh);
                unsigned g0 = (unsigned)(base + (2 * k) * THREADS + tid);
                if (g0 == mn)           { wx = ax; wy = ay; wz = az; }
                if (g0 + THREADS == mn) { wx = ah; wy = yh; wz = zh; }
            }
        }
        unsigned bal = __ballot_sync(0xffffffffu, owner);
        int wl = __ffs(bal) - 1;
        wx = __shfl_sync(0xffffffffu, wx, wl);
        wy = __shfl_sync(0xffffffffu, wy, wl);
        wz = __shfl_sync(0xffffffffu, wz, wl);

        // ---- lanes 0-7: push this warp's candidate to CTA `lane` ----
        if (lane < CLUSTER) {
            unsigned long long pk =
                ((unsigned long long)mx << 32) | (unsigned)(~mn);
            unsigned long long xyp = f2_pack(wx, wy);
            asm volatile("st.shared::cluster.b64 [%0], %1;"
                         :: "r"(rpk[parity]), "l"(pk) : "memory");
            asm volatile("st.shared::cluster.b64 [%0], %1;"
                         :: "r"(rxy[parity]), "l"(xyp) : "memory");
            asm volatile("st.shared::cluster.b32 [%0], %1;"
                         :: "r"(rz[parity]), "r"(__float_as_uint(wz)) : "memory");
            asm volatile(
                "mbarrier.arrive.release.cluster.shared::cluster.b64 _, [%0];"
                :: "r"(rmb[parity]) : "memory");
        }

        // ---- wait for all 128 candidates (acquire) ----
        asm volatile(
            "{\n\t.reg .pred P;\n"
            "WAITLP_%=:\n\t"
            "mbarrier.try_wait.parity.acquire.cluster.shared::cta.b64 P, [%0], %1, 0x989680;\n\t"
            "@!P bra WAITLP_%=;\n\t}"
            :: "r"(l_mb[parity]), "r"(phase) : "memory");

        // ---- every warp reduces the 128 slots (no block sync needed) ----
        unsigned long long pk0 = s_pk[parity][lane];
        unsigned long long pk1 = s_pk[parity][lane + 32];
        unsigned long long pk2 = s_pk[parity][lane + 64];
        unsigned long long pk3 = s_pk[parity][lane + 96];
        unsigned long long bp = u64max(u64max(pk0, pk1), u64max(pk2, pk3));

        unsigned hib = (unsigned)(bp >> 32);
        unsigned mx2 = __reduce_max_sync(0xffffffffu, hib);
        unsigned gi  = ~(unsigned)bp;
        unsigned c2  = (hib == mx2) ? gi : 0xffffffffu;
        unsigned mn2 = __reduce_min_sync(0xffffffffu, c2);
        unsigned long long wpk =
            ((unsigned long long)mx2 << 32) | (unsigned)(~mn2);

        int si = -1;
        if (pk0 == wpk) si = lane;
        if (pk1 == wpk) si = lane + 32;
        if (pk2 == wpk) si = lane + 64;
        if (pk3 == wpk) si = lane + 96;
        unsigned bal2 = __ballot_sync(0xffffffffu, si >= 0);
        int sl = __ffs(bal2) - 1;
        int sw = __shfl_sync(0xffffffffu, si, sl);

        far = (int)mn2;
        float ncx, ncy;
        f2_unpack(s_xy[parity][sw], ncx, ncy);
        float ncz = __uint_as_float(s_z[parity][sw]);
        ncx2 = f2_pack(-ncx, -ncx);
        ncy2 = f2_pack(-ncy, -ncy);
        ncz2 = f2_pack(-ncz, -ncz);
    }

    // Drain: no CTA exits while peers may still address its SMEM
    asm volatile("barrier.cluster.arrive.aligned;" ::: "memory");
    asm volatile("barrier.cluster.wait.aligned;" ::: "memory");
}

// ---------------------------------------------------------------------------
// Gather epilogue: out = concat( sampled_xyz [B,3,M], sampled_feature [B,Cin,M] )
// ---------------------------------------------------------------------------
__global__ void gather_kernel(const float* __restrict__ xyz,
                              const float* __restrict__ feat,
                              float* __restrict__ out)
{
    const int P1  = Bn * 3 * Mn;
    const int TOT = P1 + Bn * CINn * Mn;
    int t = blockIdx.x * blockDim.x + threadIdx.x;
    if (t >= TOT) return;
    if (t < P1) {
        int b = t / (3 * Mn);
        int rem = t - b * 3 * Mn;
        int c = rem / Mn;
        int m = rem - c * Mn;
        int idx = g_idx[b * Mn + m];
        out[t] = xyz[(size_t)b * 3 * Nn + (size_t)c * Nn + idx];
    } else {
        int u = t - P1;
        int b = u / (CINn * Mn);
        int rem = u - b * CINn * Mn;
        int c = rem / Mn;
        int m = rem - c * Mn;
        int idx = g_idx[b * Mn + m];
        out[t] = feat[(size_t)b * CINn * Nn + (size_t)c * Nn + idx];
    }
}

extern "C" void kernel_launch(void* const* d_in, const int* in_sizes, int n_in,
                              void* d_out, int out_size)
{
    const float* xyz  = (const float*)d_in[0];  // [B,3,N]
    const float* feat = (const float*)d_in[1];  // [B,Cin,N]
    float* out = (float*)d_out;

    fps_kernel<<<Bn * CLUSTER, THREADS>>>(xyz);

    const int TOT = Bn * 3 * Mn + Bn * CINn * Mn;
    gather_kernel<<<(TOT + 255) / 256, 256>>>(xyz, feat, out);
}

// round 17
// speedup vs baseline: 1.0198x; 1.0001x over previous
#include <cuda_runtime.h>
#include <cstdint>

// Problem constants (fixed by the reference)
#define Bn       8
#define Nn       32768
#define CINn     128
#define Mn       (Nn / 4)          // 8192 sampled points
#define CLUSTER  8                 // CTAs per batch (one cluster)
#define PTS_CTA  (Nn / CLUSTER)    // 4096 points per CTA
#define THREADS  512
#define PTS_THR  (PTS_CTA / THREADS) // 8 points per thread
#define PAIRS    (PTS_THR / 2)       // 4 f32x2 pairs per thread
#define NWARPS   (THREADS / 32)      // 16
#define SLOTS    (CLUSTER * NWARPS)  // 128 candidate slots per CTA

// Scratch: selected indices per batch (allowed: __device__ global, no alloc)
__device__ int g_idx[Bn * Mn];

__device__ __forceinline__ uint32_t smem_u32(const void* p) {
    return (uint32_t)__cvta_generic_to_shared(p);
}
__device__ __forceinline__ uint32_t mapa_u32(uint32_t laddr, uint32_t cta) {
    uint32_t r;
    asm("mapa.shared::cluster.u32 %0, %1, %2;" : "=r"(r) : "r"(laddr), "r"(cta));
    return r;
}

// ---- f32x2 packed fp32 helpers (each half = independent rn op, bit-exact) ----
__device__ __forceinline__ void f2_add(unsigned long long& d,
                                       unsigned long long a, unsigned long long b) {
    asm("add.rn.f32x2 %0, %1, %2;" : "=l"(d) : "l"(a), "l"(b));
}
__device__ __forceinline__ void f2_mul(unsigned long long& d,
                                       unsigned long long a, unsigned long long b) {
    asm("mul.rn.f32x2 %0, %1, %2;" : "=l"(d) : "l"(a), "l"(b));
}
__device__ __forceinline__ void f2_fma(unsigned long long& d, unsigned long long a,
                                       unsigned long long b, unsigned long long c) {
    asm("fma.rn.f32x2 %0, %1, %2, %3;" : "=l"(d) : "l"(a), "l"(b), "l"(c));
}
__device__ __forceinline__ unsigned long long f2_pack(float lo, float hi) {
    unsigned long long r;
    asm("mov.b64 %0, {%1, %2};" : "=l"(r) : "f"(lo), "f"(hi));
    return r;
}
__device__ __forceinline__ void f2_unpack(unsigned long long v, float& lo, float& hi) {
    asm("mov.b64 {%0, %1}, %2;" : "=f"(lo), "=f"(hi) : "l"(v));
}
__device__ __forceinline__ unsigned long long u64max(unsigned long long a,
                                                     unsigned long long b) {
    return a > b ? a : b;
}

// ---------------------------------------------------------------------------
// FPS: one 8-CTA cluster per batch, points/distances register-resident.
// Single-level cross-SM argmax: each warp pushes its candidate straight to all
// 8 CTAs (lanes 0-7, precomputed mapa addrs) + mbarrier arrive (count=128).
// Every warp redundantly reduces the 128 slots after the wait — no block
// barriers anywhere in the iteration. Numerics frozen: tie->lowest index,
// d = fma(dz,dz, fma(dx,dx, dy*dy)), dx = px + (-cx).
// ---------------------------------------------------------------------------
__global__ void __cluster_dims__(CLUSTER, 1, 1) __launch_bounds__(THREADS, 1)
fps_kernel(const float* __restrict__ xyz)
{
    __shared__ unsigned long long s_pk[2][SLOTS];   // (dist_bits<<32) | ~idx
    __shared__ unsigned long long s_xy[2][SLOTS];   // packed (x,y)
    __shared__ unsigned           s_z [2][SLOTS];   // z bits
    __shared__ unsigned long long s_mb[2];          // parity mbarriers

    const int tid  = threadIdx.x;
    const int lane = tid & 31;
    const int warp = tid >> 5;
    const int b    = blockIdx.x / CLUSTER;
    const int rank = blockIdx.x % CLUSTER;

    const float* __restrict__ xb = xyz + (size_t)b * 3 * Nn;
    const float* __restrict__ yb = xb + Nn;
    const float* __restrict__ zb = xb + 2 * Nn;
    const int base = rank * PTS_CTA;

    if (tid == 0) {
        asm volatile("mbarrier.init.shared.b64 [%0], %1;"
                     :: "r"(smem_u32(&s_mb[0])), "r"(SLOTS) : "memory");
        asm volatile("mbarrier.init.shared.b64 [%0], %1;"
                     :: "r"(smem_u32(&s_mb[1])), "r"(SLOTS) : "memory");
    }
    asm volatile("barrier.cluster.arrive.aligned;" ::: "memory");

    // Register-resident point slice (f32x2 pairs) + running min-distance
    unsigned long long pxu[PAIRS], pyu[PAIRS], pzu[PAIRS];
    float dist[PTS_THR];
#pragma unroll
    for (int k = 0; k < PAIRS; k++) {
        int g0 = base + (2 * k) * THREADS + tid;
        int g1 = g0 + THREADS;
        pxu[k] = f2_pack(xb[g0], xb[g1]);
        pyu[k] = f2_pack(yb[g0], yb[g1]);
        pzu[k] = f2_pack(zb[g0], zb[g1]);
        dist[2 * k] = 1e10f;
        dist[2 * k + 1] = 1e10f;
    }

    // Precompute remote push addresses (lane l -> CTA l); slot = rank*16+warp
    const int myslot = rank * NWARPS + warp;
    const uint32_t tgt = (uint32_t)(lane & (CLUSTER - 1));
    uint32_t rpk[2], rxy[2], rz[2], rmb[2];
#pragma unroll
    for (int p = 0; p < 2; p++) {
        rpk[p] = mapa_u32(smem_u32(&s_pk[p][myslot]), tgt);
        rxy[p] = mapa_u32(smem_u32(&s_xy[p][myslot]), tgt);
        rz [p] = mapa_u32(smem_u32(&s_z [p][myslot]), tgt);
        rmb[p] = mapa_u32(smem_u32(&s_mb[p]), tgt);
    }
    const uint32_t l_mb[2] = { smem_u32(&s_mb[0]), smem_u32(&s_mb[1]) };

    // Initial farthest = point 0 (reference seeds index 0)
    float c0x = xb[0], c0y = yb[0], c0z = zb[0];
    unsigned long long ncx2 = f2_pack(-c0x, -c0x);
    unsigned long long ncy2 = f2_pack(-c0y, -c0y);
    unsigned long long ncz2 = f2_pack(-c0z, -c0z);
    int far = 0;

    asm volatile("barrier.cluster.wait.aligned;" ::: "memory");

    for (int i = 0; i < Mn; i++) {
        if (rank == 0 && tid == 0) g_idx[b * Mn + i] = far;
        const int parity = i & 1;
        const unsigned phase = (unsigned)((i >> 1) & 1);

        // ---- update distances (f32x2, frozen rounding) + thread argmax ----
        float bd = -1.0f;
        unsigned bi = 0;
#pragma unroll
        for (int k = 0; k < PAIRS; k++) {
            unsigned long long dx2, dy2, dz2, t;
            f2_add(dx2, pxu[k], ncx2);          // px - cx  (exact: a + (-b))
            f2_add(dy2, pyu[k], ncy2);
            f2_add(dz2, pzu[k], ncz2);
            f2_mul(t, dy2, dy2);
            f2_fma(t, dx2, dx2, t);             // fma(dx,dx, dy*dy)
            f2_fma(t, dz2, dz2, t);             // fma(dz,dz, ...)
            float d0, d1;
            f2_unpack(t, d0, d1);
            float nd0 = fminf(dist[2 * k], d0);     dist[2 * k] = nd0;
            float nd1 = fminf(dist[2 * k + 1], d1); dist[2 * k + 1] = nd1;
            unsigned g0 = (unsigned)(base + (2 * k) * THREADS + tid);
            if (nd0 > bd) { bd = nd0; bi = g0; }            // strict >: lowest idx
            if (nd1 > bd) { bd = nd1; bi = g0 + THREADS; }
        }

        // ---- warp argmax (redux): max dist bits, min idx among max ----
        unsigned bits = __float_as_uint(bd);                // bd >= 0 always
        unsigned mx = __reduce_max_sync(0xffffffffu, bits);
        unsigned cand = (bits == mx) ? bi : 0xffffffffu;
        unsigned mn = __reduce_min_sync(0xffffffffu, cand);

        // ---- owner lane extracts winner xyz, broadcast to lanes 0-7 ----
        bool owner = (bits == mx) && (bi == mn);
        float wx = 0.f, wy = 0.f, wz = 0.f;
        if (owner) {
#pragma unroll
            for (int k = 0; k < PAIRS; k++) {
                float ax, ah, ay, yh, az, zh;
                f2_unpack(pxu[k], ax, ah);
                f2_unpack(pyu[k], ay, yh);
                f2_unpack(pzu[k], az, zh);
                unsigned g0 = (unsigned)(base + (2 * k) * THREADS + tid);
                if (g0 == mn)           { wx = ax; wy = ay; wz = az; }
                if (g0 + THREADS == mn) { wx = ah; wy = yh; wz = zh; }
            }
        }
        unsigned bal = __ballot_sync(0xffffffffu, owner);
        int wl = __ffs(bal) - 1;
        wx = __shfl_sync(0xffffffffu, wx, wl);
        wy = __shfl_sync(0xffffffffu, wy, wl);
        wz = __shfl_sync(0xffffffffu, wz, wl);

        // ---- lanes 0-7: push this warp's candidate to CTA `lane` ----
        if (lane < CLUSTER) {
            unsigned long long pk =
                ((unsigned long long)mx << 32) | (unsigned)(~mn);
            unsigned long long xyp = f2_pack(wx, wy);
            asm volatile("st.shared::cluster.b64 [%0], %1;"
                         :: "r"(rpk[parity]), "l"(pk) : "memory");
            asm volatile("st.shared::cluster.b64 [%0], %1;"
                         :: "r"(rxy[parity]), "l"(xyp) : "memory");
            asm volatile("st.shared::cluster.b32 [%0], %1;"
                         :: "r"(rz[parity]), "r"(__float_as_uint(wz)) : "memory");
            asm volatile(
                "mbarrier.arrive.release.cluster.shared::cluster.b64 _, [%0];"
                :: "r"(rmb[parity]) : "memory");
        }

        // ---- wait for all 128 candidates (acquire) ----
        asm volatile(
            "{\n\t.reg .pred P;\n"
            "WAITLP_%=:\n\t"
            "mbarrier.try_wait.parity.acquire.cluster.shared::cta.b64 P, [%0], %1, 0x989680;\n\t"
            "@!P bra WAITLP_%=;\n\t}"
            :: "r"(l_mb[parity]), "r"(phase) : "memory");

        // ---- every warp reduces the 128 slots (no block sync needed) ----
        unsigned long long pk0 = s_pk[parity][lane];
        unsigned long long pk1 = s_pk[parity][lane + 32];
        unsigned long long pk2 = s_pk[parity][lane + 64];
        unsigned long long pk3 = s_pk[parity][lane + 96];
        unsigned long long bp = u64max(u64max(pk0, pk1), u64max(pk2, pk3));

        unsigned hib = (unsigned)(bp >> 32);
        unsigned mx2 = __reduce_max_sync(0xffffffffu, hib);
        unsigned gi  = ~(unsigned)bp;
        unsigned c2  = (hib == mx2) ? gi : 0xffffffffu;
        unsigned mn2 = __reduce_min_sync(0xffffffffu, c2);
        unsigned long long wpk =
            ((unsigned long long)mx2 << 32) | (unsigned)(~mn2);

        int si = -1;
        if (pk0 == wpk) si = lane;
        if (pk1 == wpk) si = lane + 32;
        if (pk2 == wpk) si = lane + 64;
        if (pk3 == wpk) si = lane + 96;
        unsigned bal2 = __ballot_sync(0xffffffffu, si >= 0);
        int sl = __ffs(bal2) - 1;
        int sw = __shfl_sync(0xffffffffu, si, sl);

        far = (int)mn2;
        float ncx, ncy;
        f2_unpack(s_xy[parity][sw], ncx, ncy);
        float ncz = __uint_as_float(s_z[parity][sw]);
        ncx2 = f2_pack(-ncx, -ncx);
        ncy2 = f2_pack(-ncy, -ncy);
        ncz2 = f2_pack(-ncz, -ncz);
    }

    // Drain: no CTA exits while peers may still address its SMEM
    asm volatile("barrier.cluster.arrive.aligned;" ::: "memory");
    asm volatile("barrier.cluster.wait.aligned;" ::: "memory");
}

// ---------------------------------------------------------------------------
// Gather epilogue: out = concat( sampled_xyz [B,3,M], sampled_feature [B,Cin,M] )
// ---------------------------------------------------------------------------
__global__ void gather_kernel(const float* __restrict__ xyz,
                              const float* __restrict__ feat,
                              float* __restrict__ out)
{
    const int P1  = Bn * 3 * Mn;
    const int TOT = P1 + Bn * CINn * Mn;
    int t = blockIdx.x * blockDim.x + threadIdx.x;
    if (t >= TOT) return;
    if (t < P1) {
        int b = t / (3 * Mn);
        int rem = t - b * 3 * Mn;
        int c = rem / Mn;
        int m = rem - c * Mn;
        int idx = g_idx[b * Mn + m];
        out[t] = xyz[(size_t)b * 3 * Nn + (size_t)c * Nn + idx];
    } else {
        int u = t - P1;
        int b = u / (CINn * Mn);
        int rem = u - b * CINn * Mn;
        int c = rem / Mn;
        int m = rem - c * Mn;
        int idx = g_idx[b * Mn + m];
        out[t] = feat[(size_t)b * CINn * Nn + (size_t)c * Nn + idx];
    }
}

extern "C" void kernel_launch(void* const* d_in, const int* in_sizes, int n_in,
                              void* d_out, int out_size)
{
    const float* xyz  = (const float*)d_in[0];  // [B,3,N]
    const float* feat = (const float*)d_in[1];  // [B,Cin,N]
    float* out = (float*)d_out;

    fps_kernel<<<Bn * CLUSTER, THREADS>>>(xyz);

    const int TOT = Bn * 3 * Mn + Bn * CINn * Mn;
    gather_kernel<<<(TOT + 255) / 256, 256>>>(xyz, feat, out);
}